// round 16
// baseline (speedup 1.0000x reference)
#include <cuda_runtime.h>
#include <cuda_bf16.h>

// EdgeToVertex: tril(x) * 257x257 "plus" kernel, stride (256,1), SAME
// -> out [512, 1, 256, 1].
//
// out[b,w] = colsum(w)                 colsum(w) = sum_{r=w..255} x[b,r,w]
//          + S                          S = sum_{c=0..128} x[b,128,c]
//          - 2*x[b,128,w]     (w<=128)
//          - prefix128(w-129) (w>=129)
//
// R15 (resubmit; previous round died to a container infra failure):
// R14 (init writes correction into out; capped branch-free main with REDG;
// PDL overlap) with init's grid shrunk 4x: 128 CTAs, each scanning 4 images
// (row-128 values prefetched with MLP 4). Less SM-slot interference with
// main's first wave during the PDL overlap window.

#define NN 256
#define NB 512
#define RB 64
#define NBLK (NN / RB)     // 4
#define RPT 16             // rows per thread
#define IMG_PER 4          // images per init CTA

__global__ __launch_bounds__(256) void etv_init(const float* __restrict__ x,
                                                float* __restrict__ out) {
    const int w    = threadIdx.x;
    const int b0   = blockIdx.x * IMG_PER;
    const int lane = w & 31;
    const int wrp  = w >> 5;

    // Prefetch row-128 values for all 4 images (independent loads).
    float myv[IMG_PER];
    #pragma unroll
    for (int k = 0; k < IMG_PER; ++k) {
        const float* X = x + (size_t)(b0 + k) * (NN * NN);
        myv[k] = (w <= 128) ? X[128 * NN + w] : 0.f;
    }

    __shared__ float wsum[8];
    __shared__ float sdata[NN];

    #pragma unroll
    for (int k = 0; k < IMG_PER; ++k) {
        // Inclusive prefix scan over 256 cols: shfl in-warp + cross-warp.
        float v = myv[k];
        #pragma unroll
        for (int off = 1; off < 32; off <<= 1) {
            float n = __shfl_up_sync(0xffffffff, v, off);
            if (lane >= off) v += n;
        }
        if (lane == 31) wsum[wrp] = v;
        __syncthreads();
        float base = 0.f;
        #pragma unroll
        for (int j = 0; j < 7; ++j)
            if (j < wrp) base += wsum[j];
        sdata[w] = v + base;               // inclusive prefix of row 128
        __syncthreads();

        const float S = sdata[128];
        const float corr = (w <= 128) ? (S - 2.0f * myv[k])
                                      : (S - sdata[w - 129]);
        out[(b0 + k) * NN + w] = corr;     // init output with correction term
        __syncthreads();                   // sdata/wsum reuse across k
    }

    cudaTriggerProgrammaticLaunchCompletion();
}

__global__ __launch_bounds__(256, 8) void etv_main(const float* __restrict__ x,
                                                   float* __restrict__ out) {
    const int blk = blockIdx.x;            // row block 0..3 (interleaved order)
    const int b   = blockIdx.y;            // batch
    const int t   = threadIdx.x;
    const int c4     = t & 63;             // column group (cols 4c4..4c4+3)
    const int rowOff = t >> 6;             // 0..3 -> 16 rows each
    const int r0  = blk * RB + rowOff * RPT;
    const int cbase = c4 * 4;
    const float* __restrict__ X = x + (size_t)b * (NN * NN);
    const float* p = X + r0 * NN + cbase;

    float4 acc = make_float4(0.f, 0.f, 0.f, 0.f);

    #pragma unroll
    for (int i = 0; i < RPT; ++i) {
        const int r = r0 + i;
        if (cbase <= r) {                  // at least one component in tril
            float4 v = *reinterpret_cast<const float4*>(p + i * NN);
            const int d = r - cbase;       // 0..3 => straddles the diagonal
            if (d < 3) {
                if (d < 1) v.y = 0.f;
                if (d < 2) v.z = 0.f;
                v.w = 0.f;
            }
            acc.x += v.x; acc.y += v.y; acc.z += v.z; acc.w += v.w;
        }
    }

    // Reduce the 4 row groups per column group.
    __shared__ float4 part[4][64];
    part[rowOff][c4] = acc;
    __syncthreads();

    if (t < 64) {
        float4 s = part[0][t];
        #pragma unroll
        for (int j = 1; j < 4; ++j) {
            float4 p4 = part[j][t];
            s.x += p4.x; s.y += p4.y; s.z += p4.z; s.w += p4.w;
        }

        // Wait for etv_init's correction stores before accumulating.
        cudaGridDependencySynchronize();

        const int lastrow = blk * RB + RB - 1;
        float* o = &out[b * NN + t * 4];
        if (t * 4     <= lastrow) atomicAdd(o + 0, s.x);
        if (t * 4 + 1 <= lastrow) atomicAdd(o + 1, s.y);
        if (t * 4 + 2 <= lastrow) atomicAdd(o + 2, s.z);
        if (t * 4 + 3 <= lastrow) atomicAdd(o + 3, s.w);
    }
}

extern "C" void kernel_launch(void* const* d_in, const int* in_sizes, int n_in,
                              void* d_out, int out_size) {
    const float* x = (const float*)d_in[0];
    if (n_in > 1 && in_sizes[0] != NB * NN * NN) {
        for (int i = 0; i < n_in; ++i) {
            if (in_sizes[i] == NB * NN * NN) { x = (const float*)d_in[i]; break; }
        }
    }
    float* out = (float*)d_out;

    etv_init<<<NB / IMG_PER, NN>>>(x, out);

    // Launch main with Programmatic Dependent Launch so it overlaps init.
    cudaLaunchAttribute attrs[1];
    attrs[0].id = cudaLaunchAttributeProgrammaticStreamSerialization;
    attrs[0].val.programmaticStreamSerializationAllowed = 1;

    cudaLaunchConfig_t cfg = {};
    cfg.gridDim  = dim3(NBLK, NB);
    cfg.blockDim = dim3(NN);
    cfg.dynamicSmemBytes = 0;
    cfg.stream = 0;                        // legacy stream (capture target)
    cfg.attrs = attrs;
    cfg.numAttrs = 1;

    cudaLaunchKernelEx(&cfg, etv_main, x, out);
}

// round 17
// speedup vs baseline: 1.0800x; 1.0800x over previous
#include <cuda_runtime.h>
#include <cuda_bf16.h>

// EdgeToVertex: tril(x) * 257x257 "plus" kernel, stride (256,1), SAME
// -> out [512, 1, 256, 1].
//
// out[b,w] = colsum(w)                 colsum(w) = sum_{r=w..255} x[b,r,w]
//          + S                          S = sum_{c=0..128} x[b,128,c]
//          - 2*x[b,128,w]     (w<=128)
//          - prefix128(w-129) (w>=129)
//
// R17: single-wave main kernel. RB=128 -> grid (2,512) = 1024 CTAs at
// 8 CTAs/SM = one resident wave (no wave transition, no tail). Thread t owns
// float4 column group c4=t&63 over 32 rows (32 predicated LDG.128), smem
// reduce over 4 row groups of 32, 256 REDG per CTA. Init kernel (R14's
// 512-CTA version) writes the row-128 prefix-scan correction into out and is
// overlapped via PDL; main waits only before its atomic phase.

#define NN 256
#define NB 512
#define RB 128
#define NBLK (NN / RB)     // 2
#define RPT 32             // rows per thread

__global__ __launch_bounds__(256) void etv_init(const float* __restrict__ x,
                                                float* __restrict__ out) {
    const int b = blockIdx.x;
    const int w = threadIdx.x;
    const float* __restrict__ X = x + (size_t)b * (NN * NN);

    // Row 128 of tril keeps cols 0..128.
    const float myv = (w <= 128) ? X[128 * NN + w] : 0.f;

    // Inclusive prefix scan over 256 cols: shfl in-warp + cross-warp offsets.
    __shared__ float wsum[8];
    __shared__ float sdata[NN];
    const int lane = w & 31;
    const int wrp  = w >> 5;
    float v = myv;
    #pragma unroll
    for (int off = 1; off < 32; off <<= 1) {
        float n = __shfl_up_sync(0xffffffff, v, off);
        if (lane >= off) v += n;
    }
    if (lane == 31) wsum[wrp] = v;
    __syncthreads();
    float base = 0.f;
    #pragma unroll
    for (int j = 0; j < 7; ++j)
        if (j < wrp) base += wsum[j];
    sdata[w] = v + base;                   // inclusive prefix of row 128
    __syncthreads();

    const float S = sdata[128];
    const float corr = (w <= 128) ? (S - 2.0f * myv) : (S - sdata[w - 129]);
    out[b * NN + w] = corr;                // init output with correction term

    cudaTriggerProgrammaticLaunchCompletion();
}

__global__ __launch_bounds__(256, 8) void etv_main(const float* __restrict__ x,
                                                   float* __restrict__ out) {
    const int blk = blockIdx.x;            // row block 0..1 (128 rows each)
    const int b   = blockIdx.y;            // batch
    const int t   = threadIdx.x;
    const int c4     = t & 63;             // column group (cols 4c4..4c4+3)
    const int rowOff = t >> 6;             // 0..3 -> 32 rows each
    const int r0  = blk * RB + rowOff * RPT;
    const int cbase = c4 * 4;
    const float* __restrict__ X = x + (size_t)b * (NN * NN);
    const float* p = X + r0 * NN + cbase;

    float4 acc = make_float4(0.f, 0.f, 0.f, 0.f);

    #pragma unroll
    for (int i = 0; i < RPT; ++i) {
        const int r = r0 + i;
        if (cbase <= r) {                  // at least one component in tril
            float4 v = *reinterpret_cast<const float4*>(p + i * NN);
            const int d = r - cbase;       // 0..3 => straddles the diagonal
            if (d < 3) {
                if (d < 1) v.y = 0.f;
                if (d < 2) v.z = 0.f;
                v.w = 0.f;
            }
            acc.x += v.x; acc.y += v.y; acc.z += v.z; acc.w += v.w;
        }
    }

    // Reduce the 4 row groups per column group.
    __shared__ float4 part[4][64];
    part[rowOff][c4] = acc;
    __syncthreads();

    if (t < 64) {
        float4 s = part[0][t];
        #pragma unroll
        for (int j = 1; j < 4; ++j) {
            float4 p4 = part[j][t];
            s.x += p4.x; s.y += p4.y; s.z += p4.z; s.w += p4.w;
        }

        // Wait for etv_init's correction stores before accumulating.
        cudaGridDependencySynchronize();

        const int lastrow = blk * RB + RB - 1;
        float* o = &out[b * NN + t * 4];
        if (t * 4     <= lastrow) atomicAdd(o + 0, s.x);
        if (t * 4 + 1 <= lastrow) atomicAdd(o + 1, s.y);
        if (t * 4 + 2 <= lastrow) atomicAdd(o + 2, s.z);
        if (t * 4 + 3 <= lastrow) atomicAdd(o + 3, s.w);
    }
}

extern "C" void kernel_launch(void* const* d_in, const int* in_sizes, int n_in,
                              void* d_out, int out_size) {
    const float* x = (const float*)d_in[0];
    if (n_in > 1 && in_sizes[0] != NB * NN * NN) {
        for (int i = 0; i < n_in; ++i) {
            if (in_sizes[i] == NB * NN * NN) { x = (const float*)d_in[i]; break; }
        }
    }
    float* out = (float*)d_out;

    etv_init<<<NB, NN>>>(x, out);

    // Launch main with Programmatic Dependent Launch so it overlaps init.
    cudaLaunchAttribute attrs[1];
    attrs[0].id = cudaLaunchAttributeProgrammaticStreamSerialization;
    attrs[0].val.programmaticStreamSerializationAllowed = 1;

    cudaLaunchConfig_t cfg = {};
    cfg.gridDim  = dim3(NBLK, NB);
    cfg.blockDim = dim3(NN);
    cfg.dynamicSmemBytes = 0;
    cfg.stream = 0;                        // legacy stream (capture target)
    cfg.attrs = attrs;
    cfg.numAttrs = 1;

    cudaLaunchKernelEx(&cfg, etv_main, x, out);
}